// round 4
// baseline (speedup 1.0000x reference)
#include <cuda_runtime.h>
#include <math.h>

#define BB 32
#define NN 4096
#define CC 256
#define KK 64
#define DD 256
#define SLICES 32
#define TPS (NN/SLICES)   /* 128 tokens per CTA */
#define TCH 64            /* tokens per chunk */
#define NCH (TPS/TCH)     /* 2 chunks */
#define XS 260            /* x_s row stride (multiple of 4) */
#define LS 66             /* logits row stride */
#define HCH 256           /* hidden GEMM i-chunks */
#define IC 64             /* i per hidden chunk */

typedef unsigned long long u64;

// ---------------- device scratch (no allocations allowed) ----------------
__device__ __align__(16) float  g_vpart[(size_t)BB * SLICES * KK * CC];  // 64 MB
__device__ __align__(16) float  g_apart[BB * SLICES * KK];
__device__ __align__(16) float  g_vladn[BB * KK * CC];
__device__ __align__(16) float  g_rsq[BB * KK];
__device__ __align__(16) float  g_invb[BB];
__device__ __align__(16) float  g_hpart[HCH * BB * DD];                  // 8 MB
__device__ __align__(16) float  g_h[BB * DD];
__device__ __align__(16) float  g_y[BB * DD];
__device__ __align__(16) float  g_z[BB * DD];
__device__ __align__(16) float2 g_w2t[(CC/2) * KK];                      // 64 KB

// ---------------- f32x2 helpers (sm_100+ packed FFMA) ----------------
__device__ __forceinline__ u64 ffma2(u64 a, u64 b, u64 c) {
    u64 d;
    asm("fma.rn.f32x2 %0, %1, %2, %3;" : "=l"(d) : "l"(a), "l"(b), "l"(c));
    return d;
}
__device__ __forceinline__ u64 pack2(float lo, float hi) {
    u64 r;
    asm("mov.b64 %0, {%1, %2};" : "=l"(r) : "f"(lo), "f"(hi));
    return r;
}
__device__ __forceinline__ float2 unpack2(u64 v) {
    float2 f;
    asm("mov.b64 {%0, %1}, %2;" : "=f"(f.x), "=f"(f.y) : "l"(v));
    return f;
}

// =====================================================================
// Kernel 0: transpose conv_w -> w2t[c2][k] = (w[k][2c2], w[k][2c2+1])
// =====================================================================
__global__ __launch_bounds__(256) void k_wt(const float* __restrict__ conv_w)
{
    int idx = blockIdx.x * 256 + threadIdx.x;           // 8192 total
    if (idx < (CC/2) * KK) {
        int c2 = idx >> 6, k = idx & 63;
        g_w2t[idx] = make_float2(conv_w[k * CC + 2 * c2],
                                 conv_w[k * CC + 2 * c2 + 1]);
    }
}

// =====================================================================
// Kernel 1: fused normalize + logits + softmax + VLAD partial accumulate
// grid = (SLICES, BB), block = 512, 1 CTA/SM
// =====================================================================
__global__ __launch_bounds__(512, 1) void k_vlad(const float* __restrict__ x)
{
    extern __shared__ float smem[];
    float* w_s = smem;                      // (CC/2)*KK float2 = 16384 floats (64 KB)
    float* x_s = w_s + CC * KK / 2 * 2;     // TCH*XS floats (~65 KB)
    float* a_s = x_s + TCH * XS;            // KK*LS floats  (16.5 KB)

    const int b = blockIdx.y, sl = blockIdx.x;
    const int tid = threadIdx.x;
    const int tx = tid & 15, ty = tid >> 4;   // VLAD map: k = ty + 32q, c-pairs 2tx+32j
    const int kk8 = tid & 7, tt = tid >> 3;   // logits map: k = kk8 + 8q, t = tt

    // load transposed conv_w into shared once
    for (int i = tid; i < CC * KK / 2 / 2; i += 512) {   // 4096 float4
        float4 v = *(const float4*)((const float*)g_w2t + 4 * i);
        *(float4*)(w_s + 4 * i) = v;
    }

    // VLAD accumulators: 16 u64 = 32 regs
    u64 V2[2][8];
#pragma unroll
    for (int q = 0; q < 2; q++)
#pragma unroll
        for (int j = 0; j < 8; j++) V2[q][j] = 0ULL;
    float asum[2] = {0.f, 0.f};

    for (int ch = 0; ch < NCH; ++ch) {
        __syncthreads();
        const int n0 = sl * TPS + ch * TCH;
        const float* xg = x + ((size_t)b * NN + n0) * CC;
        for (int i = tid; i < TCH * CC / 4; i += 512) {
            int t = i >> 6, c4 = i & 63;
            float4 v = *(const float4*)(xg + t * CC + 4 * c4);
            *(float4*)(x_s + t * XS + 4 * c4) = v;
        }
        __syncthreads();

        // per-token L2 normalize over C (8 threads per token)
        {
            float s = 0.f;
#pragma unroll 8
            for (int c = kk8; c < CC; c += 8) { float v = x_s[tt * XS + c]; s = fmaf(v, v, s); }
            s += __shfl_xor_sync(0xffffffffu, s, 1);
            s += __shfl_xor_sync(0xffffffffu, s, 2);
            s += __shfl_xor_sync(0xffffffffu, s, 4);
            float inv = 1.0f / fmaxf(sqrtf(s), 1e-12f);
#pragma unroll 8
            for (int c = kk8; c < CC; c += 8) x_s[tt * XS + c] *= inv;
        }
        __syncthreads();

        // logits: l[k][t] = sum_c w[k][c]*xn[t][c]
        // thread computes 8 k-values (kk8 + 8q) for token tt
        {
            u64 acc[8];
#pragma unroll
            for (int q = 0; q < 8; q++) acc[q] = 0ULL;
            const float* xp = x_s + tt * XS;
            const float* wp = w_s + 2 * kk8;
#pragma unroll 4
            for (int c2 = 0; c2 < CC / 2; ++c2) {
                u64 xv = *(const u64*)(xp + 2 * c2);
                const float* wc = wp + c2 * (2 * KK);
#pragma unroll
                for (int q = 0; q < 8; q++)
                    acc[q] = ffma2(*(const u64*)(wc + 16 * q), xv, acc[q]);
            }
#pragma unroll
            for (int q = 0; q < 8; q++) {
                float2 f = unpack2(acc[q]);
                a_s[(kk8 + 8 * q) * LS + tt] = f.x + f.y;
            }
        }
        __syncthreads();

        // softmax over k per token (8 threads per token)
        {
            float mx = -1e30f;
#pragma unroll 8
            for (int k = kk8; k < KK; k += 8) mx = fmaxf(mx, a_s[k * LS + tt]);
            mx = fmaxf(mx, __shfl_xor_sync(0xffffffffu, mx, 1));
            mx = fmaxf(mx, __shfl_xor_sync(0xffffffffu, mx, 2));
            mx = fmaxf(mx, __shfl_xor_sync(0xffffffffu, mx, 4));
            float se = 0.f;
#pragma unroll 8
            for (int k = kk8; k < KK; k += 8) {
                float e = expf(a_s[k * LS + tt] - mx);
                a_s[k * LS + tt] = e;
                se += e;
            }
            se += __shfl_xor_sync(0xffffffffu, se, 1);
            se += __shfl_xor_sync(0xffffffffu, se, 2);
            se += __shfl_xor_sync(0xffffffffu, se, 4);
            float inv = 1.0f / se;
#pragma unroll 8
            for (int k = kk8; k < KK; k += 8) a_s[k * LS + tt] *= inv;
        }
        __syncthreads();

        // VLAD accumulate: V[k][c] += a[k][t]*xn[t][c]; k = ty, ty+32
#pragma unroll 2
        for (int t = 0; t < TCH; ++t) {
            float a0 = a_s[(ty + 0)  * LS + t];
            float a1 = a_s[(ty + 32) * LS + t];
            asum[0] += a0; asum[1] += a1;
            u64 ap0 = pack2(a0, a0), ap1 = pack2(a1, a1);
            const float* xr = x_s + t * XS + 2 * tx;
#pragma unroll
            for (int j = 0; j < 8; j++) {
                u64 xv = *(const u64*)(xr + 32 * j);
                V2[0][j] = ffma2(ap0, xv, V2[0][j]);
                V2[1][j] = ffma2(ap1, xv, V2[1][j]);
            }
        }
    }

    // store partials
    float* vp = g_vpart + ((size_t)(b * SLICES + sl) * KK) * CC;
#pragma unroll
    for (int q = 0; q < 2; q++) {
        int k = ty + 32 * q;
#pragma unroll
        for (int j = 0; j < 8; j++)
            *(u64*)(vp + k * CC + 2 * tx + 32 * j) = V2[q][j];
        if (tx == 0) g_apart[(b * SLICES + sl) * KK + k] = asum[q];
    }
}

// =====================================================================
// Kernel 2: reduce slices + centroid subtract + intra L2 norm
//           also emit per-row contribution to the global norm
// grid = (KK, BB), block = 256 (one thread per c)
// =====================================================================
__global__ __launch_bounds__(256) void k_reduce(const float* __restrict__ cent)
{
    const int k = blockIdx.x, b = blockIdx.y, c = threadIdx.x;
    float vs = 0.f;
#pragma unroll 4
    for (int s = 0; s < SLICES; ++s)
        vs += g_vpart[(((size_t)b * SLICES + s) * KK + k) * CC + c];
    float as = 0.f;
#pragma unroll 4
    for (int s = 0; s < SLICES; ++s)
        as += g_apart[(b * SLICES + s) * KK + k];
    float v = vs - as * cent[k * CC + c];

    __shared__ float red[8];
    float sq = v * v;
#pragma unroll
    for (int o = 16; o; o >>= 1) sq += __shfl_xor_sync(0xffffffffu, sq, o);
    if ((threadIdx.x & 31) == 0) red[threadIdx.x >> 5] = sq;
    __syncthreads();
    float tot = 0.f;
#pragma unroll
    for (int w = 0; w < 8; w++) tot += red[w];
    float inv = 1.0f / fmaxf(sqrtf(tot), 1e-12f);
    g_vladn[((size_t)b * KK + k) * CC + c] = v * inv;
    if (c == 0) g_rsq[b * KK + k] = tot * inv * inv;  // row norm^2 after intra-norm
}

// =====================================================================
// Kernel 3a: global L2 norm per batch row from per-row contributions
// grid = BB, block = 64
// =====================================================================
__global__ __launch_bounds__(64) void k_gnorm()
{
    const int b = blockIdx.x, k = threadIdx.x;
    float s = g_rsq[b * KK + k];
#pragma unroll
    for (int o = 16; o; o >>= 1) s += __shfl_xor_sync(0xffffffffu, s, o);
    __shared__ float red[2];
    if ((k & 31) == 0) red[k >> 5] = s;
    __syncthreads();
    if (k == 0) g_invb[b] = 1.0f / fmaxf(sqrtf(red[0] + red[1]), 1e-12f);
}

// =====================================================================
// Kernel 3b: hidden GEMM partials: [32,16384]x[16384,256], i-chunked
// grid = HCH (256), block = 512, 2 i-groups per CTA
// =====================================================================
__global__ __launch_bounds__(512, 2) void k_hidden(const float* __restrict__ hw)
{
    __shared__ float vs_s[BB * IC];   // 8 KB
    __shared__ float ps[BB * DD];     // 32 KB
    const int i0 = blockIdx.x * IC;
    const int tid = threadIdx.x;
    const int d = tid & 255, g = tid >> 8;

    for (int idx = tid; idx < BB * IC; idx += 512) {
        int bb = idx >> 6, ii = idx & 63;
        vs_s[idx] = g_vladn[(size_t)bb * (KK * CC) + i0 + ii];
    }
    __syncthreads();

    float P[BB];
#pragma unroll
    for (int bb = 0; bb < BB; bb++) P[bb] = 0.f;

    const float* wp = hw + (size_t)(i0 + g * 32) * DD + d;
#pragma unroll
    for (int i = 0; i < 32; ++i) {
        float w = wp[(size_t)i * DD];
        int ii = g * 32 + i;
#pragma unroll
        for (int bb = 0; bb < BB; bb++) P[bb] = fmaf(vs_s[bb * IC + ii], w, P[bb]);
    }

    if (g == 1) {
#pragma unroll
        for (int bb = 0; bb < BB; bb++) ps[bb * DD + d] = P[bb];
    }
    __syncthreads();
    if (g == 0) {
#pragma unroll
        for (int bb = 0; bb < BB; bb++)
            g_hpart[((size_t)blockIdx.x * BB + bb) * DD + d] = P[bb] + ps[bb * DD + d];
    }
}

// =====================================================================
// Kernel 4: reduce hidden partials, apply global inv-norm
// grid = (8, BB), block = 256
// =====================================================================
__global__ __launch_bounds__(256) void k_hreduce()
{
    __shared__ float red[8 * 33];
    const int b = blockIdx.y, dg = blockIdx.x;
    const int dl = threadIdx.x & 31, s8 = threadIdx.x >> 5;
    const int d = dg * 32 + dl;
    float s = 0.f;
#pragma unroll 8
    for (int ch = s8; ch < HCH; ch += 8)
        s += g_hpart[((size_t)ch * BB + b) * DD + d];
    red[s8 * 33 + dl] = s;
    __syncthreads();
    if (s8 == 0) {
        float t = 0.f;
#pragma unroll
        for (int w = 0; w < 8; w++) t += red[w * 33 + dl];
        g_h[b * DD + d] = t * g_invb[b];
    }
}

// =====================================================================
// Kernel 5: BatchNorm over batch (training-mode, biased var)
// =====================================================================
__global__ __launch_bounds__(DD) void k_bn2(const float* __restrict__ gamma,
                                            const float* __restrict__ beta)
{
    const int d = threadIdx.x;
    float y[BB];
    float m = 0.f;
#pragma unroll
    for (int b = 0; b < BB; b++) { y[b] = g_h[b * DD + d]; m += y[b]; }
    m *= (1.0f / BB);
    float v = 0.f;
#pragma unroll
    for (int b = 0; b < BB; b++) { float dv = y[b] - m; v = fmaf(dv, dv, v); }
    v *= (1.0f / BB);
    float rs = 1.0f / sqrtf(v + 1e-5f);
    float ga = gamma[d], be = beta[d];
#pragma unroll
    for (int b = 0; b < BB; b++)
        g_y[b * DD + d] = ga * (y[b] - m) * rs + be;
}

// =====================================================================
// Kernel 6: gating GEMM z = y @ gating_w   ([32,256]x[256,256])
// =====================================================================
__global__ __launch_bounds__(DD) void k_gate(const float* __restrict__ gw)
{
    __shared__ float yb[DD];
    const int b = blockIdx.x, d = threadIdx.x;
    yb[d] = g_y[b * DD + d];
    __syncthreads();
    float z = 0.f;
#pragma unroll 4
    for (int dd = 0; dd < DD; ++dd) z = fmaf(yb[dd], gw[dd * DD + d], z);
    g_z[b * DD + d] = z;
}

// =====================================================================
// Kernel 7: gating BN + sigmoid + multiply -> output
// =====================================================================
__global__ __launch_bounds__(DD) void k_final(const float* __restrict__ gbn_g,
                                              const float* __restrict__ gbn_b,
                                              float* __restrict__ out)
{
    const int d = threadIdx.x;
    float z[BB];
    float m = 0.f;
#pragma unroll
    for (int b = 0; b < BB; b++) { z[b] = g_z[b * DD + d]; m += z[b]; }
    m *= (1.0f / BB);
    float v = 0.f;
#pragma unroll
    for (int b = 0; b < BB; b++) { float dv = z[b] - m; v = fmaf(dv, dv, v); }
    v *= (1.0f / BB);
    float rs = 1.0f / sqrtf(v + 1e-5f);
    float gg = gbn_g[d], gb = gbn_b[d];
#pragma unroll
    for (int b = 0; b < BB; b++) {
        float zn = gg * (z[b] - m) * rs + gb;
        float gate = 1.0f / (1.0f + expf(-zn));
        out[b * DD + d] = g_y[b * DD + d] * gate;
    }
}

// =====================================================================
extern "C" void kernel_launch(void* const* d_in, const int* in_sizes, int n_in,
                              void* d_out, int out_size)
{
    (void)in_sizes; (void)n_in; (void)out_size;
    const float* x      = (const float*)d_in[0];
    const float* conv_w = (const float*)d_in[1];
    const float* cent   = (const float*)d_in[2];
    const float* hw     = (const float*)d_in[3];
    const float* gw     = (const float*)d_in[4];
    const float* bn2g   = (const float*)d_in[5];
    const float* bn2b   = (const float*)d_in[6];
    const float* gbng   = (const float*)d_in[7];
    const float* gbnb   = (const float*)d_in[8];
    float* out = (float*)d_out;

    const size_t smem1 = (size_t)(CC * KK + TCH * XS + KK * LS) * sizeof(float);
    cudaFuncSetAttribute(k_vlad, cudaFuncAttributeMaxDynamicSharedMemorySize, (int)smem1);

    k_wt<<<(CC/2 * KK + 255) / 256, 256>>>(conv_w);
    k_vlad<<<dim3(SLICES, BB), 512, smem1>>>(x);
    k_reduce<<<dim3(KK, BB), 256>>>(cent);
    k_gnorm<<<BB, 64>>>();
    k_hidden<<<HCH, 512>>>(hw);
    k_hreduce<<<dim3(8, BB), 256>>>();
    k_bn2<<<1, DD>>>(bn2g, bn2b);
    k_gate<<<BB, DD>>>(gw);
    k_final<<<1, DD>>>(gbng, gbnb, out);
}

// round 5
// speedup vs baseline: 1.2970x; 1.2970x over previous
#include <cuda_runtime.h>
#include <math.h>

#define BB 32
#define NN 4096
#define CC 256
#define KK 64
#define DD 256
#define SLICES 32
#define TPS (NN/SLICES)   /* 128 tokens per CTA */
#define TCH 64            /* tokens per chunk */
#define NCH (TPS/TCH)     /* 2 chunks */
#define XS 260            /* x_s row stride (multiple of 4) */
#define LS 66             /* logits row stride */
#define HCH 256           /* hidden GEMM i-chunks */
#define IC 64             /* i per hidden chunk */

typedef unsigned long long u64;

// ---------------- device scratch (no allocations allowed) ----------------
__device__ __align__(16) float  g_vpart[(size_t)BB * SLICES * KK * CC];  // 64 MB
__device__ __align__(16) float  g_apart[BB * SLICES * KK];
__device__ __align__(16) float  g_vladn[BB * KK * CC];
__device__ __align__(16) float  g_rsq[BB * KK];
__device__ __align__(16) float  g_invb[BB];
__device__ __align__(16) float  g_hpart[HCH * BB * DD];                  // 8 MB
__device__ __align__(16) float  g_h[BB * DD];
__device__ __align__(16) float  g_y[BB * DD];
__device__ __align__(16) float  g_z[BB * DD];
__device__ __align__(16) float2 g_w2t[(CC/2) * KK];                      // 64 KB

// ---------------- f32x2 helpers (sm_100+ packed FFMA) ----------------
__device__ __forceinline__ u64 ffma2(u64 a, u64 b, u64 c) {
    u64 d;
    asm("fma.rn.f32x2 %0, %1, %2, %3;" : "=l"(d) : "l"(a), "l"(b), "l"(c));
    return d;
}
__device__ __forceinline__ u64 pack2(float lo, float hi) {
    u64 r;
    asm("mov.b64 %0, {%1, %2};" : "=l"(r) : "f"(lo), "f"(hi));
    return r;
}
__device__ __forceinline__ float2 unpack2(u64 v) {
    float2 f;
    asm("mov.b64 {%0, %1}, %2;" : "=f"(f.x), "=f"(f.y) : "l"(v));
    return f;
}

// =====================================================================
// Kernel 0: transpose conv_w -> w2t[c2][k] = (w[k][2c2], w[k][2c2+1])
// =====================================================================
__global__ __launch_bounds__(256) void k_wt(const float* __restrict__ conv_w)
{
    int idx = blockIdx.x * 256 + threadIdx.x;           // 8192 total
    if (idx < (CC/2) * KK) {
        int c2 = idx >> 6, k = idx & 63;
        g_w2t[idx] = make_float2(conv_w[k * CC + 2 * c2],
                                 conv_w[k * CC + 2 * c2 + 1]);
    }
}

// =====================================================================
// Kernel 1: fused normalize + logits + softmax + VLAD partial accumulate
// grid = (SLICES, BB), block = 256, 2 CTAs/SM   (R3 configuration)
// =====================================================================
__global__ __launch_bounds__(256, 2) void k_vlad(const float* __restrict__ x)
{
    extern __shared__ float smem[];
    float* x_s = smem;                    // TCH*XS floats  (~66.6 KB)
    float* a_s = x_s + TCH * XS;          // KK*LS floats   (16.9 KB)

    const int b = blockIdx.y, sl = blockIdx.x;
    const int tid = threadIdx.x;
    const int tx = tid & 15, ty = tid >> 4;

    // VLAD accumulators: thread owns k in {ty+16q}, c pairs at 2tx+32j
    u64 V2[4][8];
#pragma unroll
    for (int q = 0; q < 4; q++)
#pragma unroll
        for (int j = 0; j < 8; j++) V2[q][j] = 0ULL;
    float asum[4] = {0.f, 0.f, 0.f, 0.f};

    for (int ch = 0; ch < NCH; ++ch) {
        __syncthreads();
        const int n0 = sl * TPS + ch * TCH;
        const float* xg = x + ((size_t)b * NN + n0) * CC;
        for (int i = tid; i < TCH * CC / 4; i += 256) {
            int t = i >> 6, c4 = i & 63;
            float4 v = *(const float4*)(xg + t * CC + 4 * c4);
            *(float4*)(x_s + t * XS + 4 * c4) = v;
        }
        __syncthreads();

        // per-token L2 normalize over C (4 threads per token)
        {
            int t = tid >> 2, l4 = tid & 3;
            float s = 0.f;
            for (int c = l4; c < CC; c += 4) { float v = x_s[t * XS + c]; s = fmaf(v, v, s); }
            s += __shfl_xor_sync(0xffffffffu, s, 1);
            s += __shfl_xor_sync(0xffffffffu, s, 2);
            float inv = 1.0f / fmaxf(sqrtf(s), 1e-12f);
            for (int c = l4; c < CC; c += 4) x_s[t * XS + c] *= inv;
        }
        __syncthreads();

        // logits: l[k][t] = sum_c w[k][c]*xn[t][c]; 4x4 register tile/thread
        // w read via coalesced LDG from L2/L1-resident w2t
        {
            u64 acc[4][4];
#pragma unroll
            for (int q = 0; q < 4; q++)
#pragma unroll
                for (int r = 0; r < 4; r++) acc[q][r] = 0ULL;
            const float2* wp0 = g_w2t + tx;
            const float* xp0 = x_s + ty * XS;
#pragma unroll 4
            for (int c2 = 0; c2 < CC / 2; ++c2) {
                u64 w2[4], x2[4];
#pragma unroll
                for (int q = 0; q < 4; q++)
                    w2[q] = *(const u64*)(wp0 + c2 * KK + 16 * q);
#pragma unroll
                for (int r = 0; r < 4; r++)
                    x2[r] = *(const u64*)(xp0 + r * 16 * XS + 2 * c2);
#pragma unroll
                for (int q = 0; q < 4; q++)
#pragma unroll
                    for (int r = 0; r < 4; r++)
                        acc[q][r] = ffma2(w2[q], x2[r], acc[q][r]);
            }
#pragma unroll
            for (int q = 0; q < 4; q++)
#pragma unroll
                for (int r = 0; r < 4; r++) {
                    float2 f = unpack2(acc[q][r]);
                    a_s[(tx + 16 * q) * LS + (ty + 16 * r)] = f.x + f.y;
                }
        }
        __syncthreads();

        // softmax over k per token (4 threads per token)
        {
            int t = tid >> 2, l4 = tid & 3;
            float mx = -1e30f;
            for (int k = l4; k < KK; k += 4) mx = fmaxf(mx, a_s[k * LS + t]);
            mx = fmaxf(mx, __shfl_xor_sync(0xffffffffu, mx, 1));
            mx = fmaxf(mx, __shfl_xor_sync(0xffffffffu, mx, 2));
            float se = 0.f;
            for (int k = l4; k < KK; k += 4) {
                float e = expf(a_s[k * LS + t] - mx);
                a_s[k * LS + t] = e;
                se += e;
            }
            se += __shfl_xor_sync(0xffffffffu, se, 1);
            se += __shfl_xor_sync(0xffffffffu, se, 2);
            float inv = 1.0f / se;
            for (int k = l4; k < KK; k += 4) a_s[k * LS + t] *= inv;
        }
        __syncthreads();

        // VLAD accumulate: V[k][c] += a[k][t]*xn[t][c]
#pragma unroll 2
        for (int t = 0; t < TCH; ++t) {
            float a0 = a_s[(ty + 0)  * LS + t];
            float a1 = a_s[(ty + 16) * LS + t];
            float a2 = a_s[(ty + 32) * LS + t];
            float a3 = a_s[(ty + 48) * LS + t];
            asum[0] += a0; asum[1] += a1; asum[2] += a2; asum[3] += a3;
            u64 ap[4] = {pack2(a0, a0), pack2(a1, a1), pack2(a2, a2), pack2(a3, a3)};
            const float* xr = x_s + t * XS + 2 * tx;
#pragma unroll
            for (int j = 0; j < 8; j++) {
                u64 xv = *(const u64*)(xr + 32 * j);
#pragma unroll
                for (int q = 0; q < 4; q++) V2[q][j] = ffma2(ap[q], xv, V2[q][j]);
            }
        }
    }

    // store partials
    float* vp = g_vpart + ((size_t)(b * SLICES + sl) * KK) * CC;
#pragma unroll
    for (int q = 0; q < 4; q++) {
        int k = ty + 16 * q;
#pragma unroll
        for (int j = 0; j < 8; j++)
            *(u64*)(vp + k * CC + 2 * tx + 32 * j) = V2[q][j];
        if (tx == 0) g_apart[(b * SLICES + sl) * KK + k] = asum[q];
    }
}

// =====================================================================
// Kernel 2: reduce slices + centroid subtract + intra L2 norm
//           also emit per-row contribution to the global norm
// grid = (KK, BB), block = 256 (one thread per c)
// =====================================================================
__global__ __launch_bounds__(256) void k_reduce(const float* __restrict__ cent)
{
    const int k = blockIdx.x, b = blockIdx.y, c = threadIdx.x;
    float vs = 0.f;
#pragma unroll 4
    for (int s = 0; s < SLICES; ++s)
        vs += g_vpart[(((size_t)b * SLICES + s) * KK + k) * CC + c];
    float as = 0.f;
#pragma unroll 4
    for (int s = 0; s < SLICES; ++s)
        as += g_apart[(b * SLICES + s) * KK + k];
    float v = vs - as * cent[k * CC + c];

    __shared__ float red[8];
    float sq = v * v;
#pragma unroll
    for (int o = 16; o; o >>= 1) sq += __shfl_xor_sync(0xffffffffu, sq, o);
    if ((threadIdx.x & 31) == 0) red[threadIdx.x >> 5] = sq;
    __syncthreads();
    float tot = 0.f;
#pragma unroll
    for (int w = 0; w < 8; w++) tot += red[w];
    float inv = 1.0f / fmaxf(sqrtf(tot), 1e-12f);
    g_vladn[((size_t)b * KK + k) * CC + c] = v * inv;
    if (c == 0) g_rsq[b * KK + k] = tot * inv * inv;  // row norm^2 after intra-norm
}

// =====================================================================
// Kernel 3a: global L2 norm per batch row from per-row contributions
// grid = BB, block = 64
// =====================================================================
__global__ __launch_bounds__(64) void k_gnorm()
{
    const int b = blockIdx.x, k = threadIdx.x;
    float s = g_rsq[b * KK + k];
#pragma unroll
    for (int o = 16; o; o >>= 1) s += __shfl_xor_sync(0xffffffffu, s, o);
    __shared__ float red[2];
    if ((k & 31) == 0) red[k >> 5] = s;
    __syncthreads();
    if (k == 0) g_invb[b] = 1.0f / fmaxf(sqrtf(red[0] + red[1]), 1e-12f);
}

// =====================================================================
// Kernel 3b: hidden GEMM partials: [32,16384]x[16384,256], i-chunked
// grid = HCH (256), block = 512, 2 i-groups per CTA
// =====================================================================
__global__ __launch_bounds__(512, 2) void k_hidden(const float* __restrict__ hw)
{
    __shared__ float vs_s[BB * IC];   // 8 KB
    __shared__ float ps[BB * DD];     // 32 KB
    const int i0 = blockIdx.x * IC;
    const int tid = threadIdx.x;
    const int d = tid & 255, g = tid >> 8;

    for (int idx = tid; idx < BB * IC; idx += 512) {
        int bb = idx >> 6, ii = idx & 63;
        vs_s[idx] = g_vladn[(size_t)bb * (KK * CC) + i0 + ii];
    }
    __syncthreads();

    float P[BB];
#pragma unroll
    for (int bb = 0; bb < BB; bb++) P[bb] = 0.f;

    const float* wp = hw + (size_t)(i0 + g * 32) * DD + d;
#pragma unroll
    for (int i = 0; i < 32; ++i) {
        float w = wp[(size_t)i * DD];
        int ii = g * 32 + i;
#pragma unroll
        for (int bb = 0; bb < BB; bb++) P[bb] = fmaf(vs_s[bb * IC + ii], w, P[bb]);
    }

    if (g == 1) {
#pragma unroll
        for (int bb = 0; bb < BB; bb++) ps[bb * DD + d] = P[bb];
    }
    __syncthreads();
    if (g == 0) {
#pragma unroll
        for (int bb = 0; bb < BB; bb++)
            g_hpart[((size_t)blockIdx.x * BB + bb) * DD + d] = P[bb] + ps[bb * DD + d];
    }
}

// =====================================================================
// Kernel 4: reduce hidden partials, apply global inv-norm
// grid = (8, BB), block = 256
// =====================================================================
__global__ __launch_bounds__(256) void k_hreduce()
{
    __shared__ float red[8 * 33];
    const int b = blockIdx.y, dg = blockIdx.x;
    const int dl = threadIdx.x & 31, s8 = threadIdx.x >> 5;
    const int d = dg * 32 + dl;
    float s = 0.f;
#pragma unroll 8
    for (int ch = s8; ch < HCH; ch += 8)
        s += g_hpart[((size_t)ch * BB + b) * DD + d];
    red[s8 * 33 + dl] = s;
    __syncthreads();
    if (s8 == 0) {
        float t = 0.f;
#pragma unroll
        for (int w = 0; w < 8; w++) t += red[w * 33 + dl];
        g_h[b * DD + d] = t * g_invb[b];
    }
}

// =====================================================================
// Kernel 5: BatchNorm over batch (training-mode, biased var)
// =====================================================================
__global__ __launch_bounds__(DD) void k_bn2(const float* __restrict__ gamma,
                                            const float* __restrict__ beta)
{
    const int d = threadIdx.x;
    float y[BB];
    float m = 0.f;
#pragma unroll
    for (int b = 0; b < BB; b++) { y[b] = g_h[b * DD + d]; m += y[b]; }
    m *= (1.0f / BB);
    float v = 0.f;
#pragma unroll
    for (int b = 0; b < BB; b++) { float dv = y[b] - m; v = fmaf(dv, dv, v); }
    v *= (1.0f / BB);
    float rs = 1.0f / sqrtf(v + 1e-5f);
    float ga = gamma[d], be = beta[d];
#pragma unroll
    for (int b = 0; b < BB; b++)
        g_y[b * DD + d] = ga * (y[b] - m) * rs + be;
}

// =====================================================================
// Kernel 6: gating GEMM z = y @ gating_w   ([32,256]x[256,256])
// =====================================================================
__global__ __launch_bounds__(DD) void k_gate(const float* __restrict__ gw)
{
    __shared__ float yb[DD];
    const int b = blockIdx.x, d = threadIdx.x;
    yb[d] = g_y[b * DD + d];
    __syncthreads();
    float z = 0.f;
#pragma unroll 4
    for (int dd = 0; dd < DD; ++dd) z = fmaf(yb[dd], gw[dd * DD + d], z);
    g_z[b * DD + d] = z;
}

// =====================================================================
// Kernel 7: gating BN + sigmoid + multiply -> output
// =====================================================================
__global__ __launch_bounds__(DD) void k_final(const float* __restrict__ gbn_g,
                                              const float* __restrict__ gbn_b,
                                              float* __restrict__ out)
{
    const int d = threadIdx.x;
    float z[BB];
    float m = 0.f;
#pragma unroll
    for (int b = 0; b < BB; b++) { z[b] = g_z[b * DD + d]; m += z[b]; }
    m *= (1.0f / BB);
    float v = 0.f;
#pragma unroll
    for (int b = 0; b < BB; b++) { float dv = z[b] - m; v = fmaf(dv, dv, v); }
    v *= (1.0f / BB);
    float rs = 1.0f / sqrtf(v + 1e-5f);
    float gg = gbn_g[d], gb = gbn_b[d];
#pragma unroll
    for (int b = 0; b < BB; b++) {
        float zn = gg * (z[b] - m) * rs + gb;
        float gate = 1.0f / (1.0f + expf(-zn));
        out[b * DD + d] = g_y[b * DD + d] * gate;
    }
}

// =====================================================================
extern "C" void kernel_launch(void* const* d_in, const int* in_sizes, int n_in,
                              void* d_out, int out_size)
{
    (void)in_sizes; (void)n_in; (void)out_size;
    const float* x      = (const float*)d_in[0];
    const float* conv_w = (const float*)d_in[1];
    const float* cent   = (const float*)d_in[2];
    const float* hw     = (const float*)d_in[3];
    const float* gw     = (const float*)d_in[4];
    const float* bn2g   = (const float*)d_in[5];
    const float* bn2b   = (const float*)d_in[6];
    const float* gbng   = (const float*)d_in[7];
    const float* gbnb   = (const float*)d_in[8];
    float* out = (float*)d_out;

    const size_t smem1 = (size_t)(TCH * XS + KK * LS) * sizeof(float);
    cudaFuncSetAttribute(k_vlad, cudaFuncAttributeMaxDynamicSharedMemorySize, (int)smem1);

    k_wt<<<(CC/2 * KK + 255) / 256, 256>>>(conv_w);
    k_vlad<<<dim3(SLICES, BB), 256, smem1>>>(x);
    k_reduce<<<dim3(KK, BB), 256>>>(cent);
    k_gnorm<<<BB, 64>>>();
    k_hidden<<<HCH, 512>>>(hw);
    k_hreduce<<<dim3(8, BB), 256>>>();
    k_bn2<<<1, DD>>>(bn2g, bn2b);
    k_gate<<<BB, DD>>>(gw);
    k_final<<<1, DD>>>(gbng, gbnb, out);
}